// round 2
// baseline (speedup 1.0000x reference)
#include <cuda_runtime.h>

// Bspline control-grid -> dense flow field.
// N = 400 images. Per image: read 32x32x2 fp32 control points (8 KB),
// write 192x192x2 fp32 flow (288 KB). HBM-write-bound.
//
// flow(y,x,c) = -192 * bilinear(p, qy, qx)[c]
//   qy = y*(G-1)/H, qx = x*(G-1)/W, floor clipped to [0, G-2], alpha clipped to [0,1]
// Blend order matches reference: interpolate along y first, then x.
//
// Thread map: threadIdx.x = column-pair (96), threadIdx.y strides rows (4 x 48).
// x-axis coefficients are loop-invariant per thread.

#define GH 192
#define GW 192
#define GG 32
#define TX 96      // column pairs per row (192/2)
#define TY 4       // row stride
#define NTHREADS (TX * TY)   // 384

__global__ __launch_bounds__(NTHREADS)
void bspline_flow_kernel(const float* __restrict__ in, float4* __restrict__ out)
{
    __shared__ float2 p[GG * GG];   // 8 KB control grid for this image

    const int n = blockIdx.x;
    const int tid = threadIdx.y * TX + threadIdx.x;

    // stage control grid: 2048 floats = 1024 float2, coalesced
    const float2* src = reinterpret_cast<const float2*>(in) + (size_t)n * (GG * GG);
    for (int i = tid; i < GG * GG; i += NTHREADS)
        p[i] = src[i];
    __syncthreads();

    const float coef = (float)(GG - 1) / (float)GH;   // 31/192, H==W so same for x

    // ---- loop-invariant x-axis coefficients (two pixels per thread) ----
    const int xb = threadIdx.x * 2;
    float qx0 = (float)(xb + 0) * coef;
    float fx0 = fminf(floorf(qx0), (float)(GG - 2));
    int   ix0 = (int)fx0;
    float ax0 = fminf(fmaxf(qx0 - fx0, 0.0f), 1.0f);

    float qx1 = (float)(xb + 1) * coef;
    float fx1 = fminf(floorf(qx1), (float)(GG - 2));
    int   ix1 = (int)fx1;
    float ax1 = fminf(fmaxf(qx1 - fx1, 0.0f), 1.0f);

    float4* dst = out + (size_t)n * (GH * (GW / 2));

    for (int y = threadIdx.y; y < GH; y += TY) {
        // y-axis coefficients
        float qy = (float)y * coef;
        float fy = fminf(floorf(qy), (float)(GG - 2));
        int   iy = (int)fy;
        float ay = fminf(fmaxf(qy - fy, 0.0f), 1.0f);
        const float2* row0 = p + iy * GG;
        const float2* row1 = row0 + GG;

        // pixel 0 (x = xb)
        float2 a00 = row0[ix0];
        float2 a01 = row0[ix0 + 1];
        float2 a10 = row1[ix0];
        float2 a11 = row1[ix0 + 1];
        float ty0 = fmaf(ay, a10.x - a00.x, a00.x);
        float ty1 = fmaf(ay, a11.x - a01.x, a01.x);
        float tz0 = fmaf(ay, a10.y - a00.y, a00.y);
        float tz1 = fmaf(ay, a11.y - a01.y, a01.y);
        float d0  = fmaf(ax0, ty1 - ty0, ty0);
        float d1  = fmaf(ax0, tz1 - tz0, tz0);

        // pixel 1 (x = xb + 1)
        float2 b00 = row0[ix1];
        float2 b01 = row0[ix1 + 1];
        float2 b10 = row1[ix1];
        float2 b11 = row1[ix1 + 1];
        float uy0 = fmaf(ay, b10.x - b00.x, b00.x);
        float uy1 = fmaf(ay, b11.x - b01.x, b01.x);
        float uz0 = fmaf(ay, b10.y - b00.y, b00.y);
        float uz1 = fmaf(ay, b11.y - b01.y, b01.y);
        float d2  = fmaf(ax1, uy1 - uy0, uy0);
        float d3  = fmaf(ax1, uz1 - uz0, uz0);

        float4 res;
        res.x = d0 * -192.0f;   // -d * H
        res.y = d1 * -192.0f;   // -d * W
        res.z = d2 * -192.0f;
        res.w = d3 * -192.0f;

        dst[y * TX + threadIdx.x] = res;   // STG.128, coalesced across threadIdx.x
    }
}

extern "C" void kernel_launch(void* const* d_in, const int* in_sizes, int n_in,
                              void* d_out, int out_size)
{
    const float* in = (const float*)d_in[0];
    const int n_images = in_sizes[0] / (2 * GG * GG);   // 400
    dim3 block(TX, TY);
    bspline_flow_kernel<<<n_images, block>>>(in, (float4*)d_out);
}

// round 5
// speedup vs baseline: 1.0036x; 1.0036x over previous
#include <cuda_runtime.h>

// Bspline control-grid -> dense flow field, separable two-pass.
// N = 400 images. Per image: read 32x32x2 fp32 ctrl (8 KB), write 192x192x2 fp32 (288 KB).
// Measured bottleneck (R2 profile of 1-pass version): L1/shared + issue, NOT DRAM.
//
// Pass 1: pys[y][j] = -192 * lerp_y(ctrl)  (scale folded in; lerp is linear)
//         -> 48 KB smem, 6144 float2
// Pass 2: out[y][x] = lerp_x(pys[y])  -> 4 LDS.64 + 4 FFMA + 1 STG.128 per 2 pixels

#define GH 192
#define GW 192
#define GG 32
#define TX 96      // column pairs per row (192/2)
#define TY 4       // row stride
#define NTHREADS (TX * TY)   // 384
#define P1_ITERS ((GH * GG) / NTHREADS)   // 6144 / 384 = 16

__global__ __launch_bounds__(NTHREADS)
void bspline_flow_kernel(const float* __restrict__ in, float4* __restrict__ out)
{
    __shared__ float2 pys[GH * GG];   // 48 KB y-interpolated (pre-scaled) rows

    const int n   = blockIdx.x;
    const int tid = threadIdx.y * TX + threadIdx.x;
    const float coef = (float)(GG - 1) / (float)GH;   // 31/192 (H==W)

    const float2* __restrict__ ctrl =
        reinterpret_cast<const float2*>(in) + (size_t)n * (GG * GG);

    // ---- Pass 1: y-axis blend (scaled by -192) into smem ----
    #pragma unroll
    for (int e = 0; e < P1_ITERS; e++) {
        const int idx = e * NTHREADS + tid;
        const int y = idx >> 5;        // idx / 32
        const int j = idx & 31;        // ctrl column

        float qy = (float)y * coef;
        float fy = fminf(floorf(qy), (float)(GG - 2));
        int   iy = (int)fy;
        float ay = fminf(fmaxf(qy - fy, 0.0f), 1.0f);

        const float2* __restrict__ base = ctrl + iy * GG + j;
        float2 p0 = base[0];          // coalesced 256B row reads per warp
        float2 p1 = base[GG];

        float2 r;
        r.x = fmaf(ay, p1.x - p0.x, p0.x) * -192.0f;   // -d * H folded in
        r.y = fmaf(ay, p1.y - p0.y, p0.y) * -192.0f;   // -d * W folded in
        pys[idx] = r;
    }
    __syncthreads();

    // ---- Pass 2: x-axis blend, write float4 (2 pixels) per iteration ----
    const int xb = threadIdx.x * 2;

    float qx0 = (float)(xb + 0) * coef;
    float fx0 = fminf(floorf(qx0), (float)(GG - 2));
    int   ix0 = (int)fx0;
    float ax0 = fminf(fmaxf(qx0 - fx0, 0.0f), 1.0f);

    float qx1 = (float)(xb + 1) * coef;
    float fx1 = fminf(floorf(qx1), (float)(GG - 2));
    int   ix1 = (int)fx1;
    float ax1 = fminf(fmaxf(qx1 - fx1, 0.0f), 1.0f);

    float4* dst = out + (size_t)n * (GH * (GW / 2));

    #pragma unroll 4
    for (int y = threadIdx.y; y < GH; y += TY) {
        const float2* __restrict__ row = pys + y * GG;

        float2 c0 = row[ix0];
        float2 c1 = row[ix0 + 1];
        float2 c2 = row[ix1];
        float2 c3 = row[ix1 + 1];

        float4 res;
        res.x = fmaf(ax0, c1.x - c0.x, c0.x);   // pixel 0, ch 0
        res.y = fmaf(ax0, c1.y - c0.y, c0.y);   // pixel 0, ch 1
        res.z = fmaf(ax1, c3.x - c2.x, c2.x);   // pixel 1, ch 0
        res.w = fmaf(ax1, c3.y - c2.y, c2.y);   // pixel 1, ch 1

        dst[y * TX + threadIdx.x] = res;   // STG.128, coalesced across threadIdx.x
    }
}

extern "C" void kernel_launch(void* const* d_in, const int* in_sizes, int n_in,
                              void* d_out, int out_size)
{
    const float* in = (const float*)d_in[0];
    const int n_images = in_sizes[0] / (2 * GG * GG);   // 400
    dim3 block(TX, TY);
    bspline_flow_kernel<<<n_images, block>>>(in, (float4*)d_out);
}

// round 6
// speedup vs baseline: 1.0637x; 1.0599x over previous
#include <cuda_runtime.h>

// Bspline control-grid -> dense flow field, separable two-pass, tiled.
// N = 400 images, each split across 4 CTAs of 48 rows (grid 400x4 = 1600 CTAs).
// R5 profile showed the 1-CTA/image version latency/occupancy-bound
// (occ 39.8%, issue 30%, no pipe >56%): 48KB smem capped residency and
// 400 CTAs gave an unbalanced 2.7-wave schedule. 12KB smem + 1600 CTAs fixes both.
//
// Pass 1: pys[y][j] = -192 * lerp_y(ctrl) for this CTA's 48 rows -> 12 KB smem
// Pass 2: out[y][x] = lerp_x(pys[y])  -> 4 LDS.64 + 4 FFMA + 1 STG.128 per 2 pixels

#define GH 192
#define GW 192
#define GG 32
#define TILES 4
#define ROWS (GH / TILES)     // 48 rows per CTA
#define TX 96                 // column pairs per row (192/2)
#define TY 4                  // row stride
#define NTHREADS (TX * TY)    // 384
#define P1_ITERS ((ROWS * GG) / NTHREADS)   // 1536 / 384 = 4

__global__ __launch_bounds__(NTHREADS)
void bspline_flow_kernel(const float* __restrict__ in, float4* __restrict__ out)
{
    __shared__ float2 pys[ROWS * GG];   // 12 KB y-interpolated (pre-scaled) rows

    const int n       = blockIdx.x;           // image
    const int rowBase = blockIdx.y * ROWS;    // first row of this tile
    const int tid     = threadIdx.y * TX + threadIdx.x;
    const float coef  = (float)(GG - 1) / (float)GH;   // 31/192 (H==W)

    const float2* __restrict__ ctrl =
        reinterpret_cast<const float2*>(in) + (size_t)n * (GG * GG);

    // ---- Pass 1: y-axis blend (scaled by -192) into smem ----
    #pragma unroll
    for (int e = 0; e < P1_ITERS; e++) {
        const int idx = e * NTHREADS + tid;
        const int y = rowBase + (idx >> 5);   // global row
        const int j = idx & 31;               // ctrl column

        float qy = (float)y * coef;
        float fy = fminf(floorf(qy), (float)(GG - 2));
        int   iy = (int)fy;
        float ay = fminf(fmaxf(qy - fy, 0.0f), 1.0f);

        const float2* __restrict__ base = ctrl + iy * GG + j;
        float2 p0 = base[0];          // coalesced 256B row reads per warp (L1/L2 hit)
        float2 p1 = base[GG];

        float2 r;
        r.x = fmaf(ay, p1.x - p0.x, p0.x) * -192.0f;   // -d * H folded in
        r.y = fmaf(ay, p1.y - p0.y, p0.y) * -192.0f;   // -d * W folded in
        pys[idx] = r;
    }
    __syncthreads();

    // ---- Pass 2: x-axis blend, write float4 (2 pixels) per iteration ----
    const int xb = threadIdx.x * 2;

    float qx0 = (float)(xb + 0) * coef;
    float fx0 = fminf(floorf(qx0), (float)(GG - 2));
    int   ix0 = (int)fx0;
    float ax0 = fminf(fmaxf(qx0 - fx0, 0.0f), 1.0f);

    float qx1 = (float)(xb + 1) * coef;
    float fx1 = fminf(floorf(qx1), (float)(GG - 2));
    int   ix1 = (int)fx1;
    float ax1 = fminf(fmaxf(qx1 - fx1, 0.0f), 1.0f);

    float4* dst = out + (size_t)n * (GH * (GW / 2)) + (size_t)rowBase * (GW / 2);

    #pragma unroll
    for (int yl = threadIdx.y; yl < ROWS; yl += TY) {
        const float2* __restrict__ row = pys + yl * GG;

        float2 c0 = row[ix0];
        float2 c1 = row[ix0 + 1];
        float2 c2 = row[ix1];
        float2 c3 = row[ix1 + 1];

        float4 res;
        res.x = fmaf(ax0, c1.x - c0.x, c0.x);   // pixel 0, ch 0
        res.y = fmaf(ax0, c1.y - c0.y, c0.y);   // pixel 0, ch 1
        res.z = fmaf(ax1, c3.x - c2.x, c2.x);   // pixel 1, ch 0
        res.w = fmaf(ax1, c3.y - c2.y, c2.y);   // pixel 1, ch 1

        dst[yl * TX + threadIdx.x] = res;   // STG.128, coalesced across threadIdx.x
    }
}

extern "C" void kernel_launch(void* const* d_in, const int* in_sizes, int n_in,
                              void* d_out, int out_size)
{
    const float* in = (const float*)d_in[0];
    const int n_images = in_sizes[0] / (2 * GG * GG);   // 400
    dim3 grid(n_images, TILES);
    dim3 block(TX, TY);
    bspline_flow_kernel<<<grid, block>>>(in, (float4*)d_out);
}

// round 8
// speedup vs baseline: 1.1861x; 1.1151x over previous
#include <cuda_runtime.h>

// Bspline control-grid -> dense flow field, separable two-pass, tiled.
// N = 400 images, each split across 8 CTAs of 24 rows (grid 400x8 = 3200 CTAs).
//
// Steady-state model (R6): harness graph-replay must drain 118 MB of dirty
// output lines to DRAM per iteration -> sustained ~4.7 TB/s write BW, i.e. the
// kernel is DRAM-writeback-bound with floor ~22-23 us. Changes vs R6 profile:
//   * __stcs streaming stores (output is write-once, never read)
//   * TILES 8 (6 KB smem): shorter pass-1 serial head, finer wave granularity
//   * pointer-strided pass-2 loop (fewer IMADs per iteration)
//
// Pass 1: pys[y][j] = -192 * lerp_y(ctrl) for this CTA's 24 rows -> 6 KB smem
// Pass 2: out[y][x] = lerp_x(pys[y])  -> 4 LDS.64 + 4 FFMA + 1 STG.128.CS per 2 px

#define GH 192
#define GW 192
#define GG 32
#define TILES 8
#define ROWS (GH / TILES)     // 24 rows per CTA
#define TX 96                 // column pairs per row (192/2)
#define TY 4                  // row stride
#define NTHREADS (TX * TY)    // 384
#define P1_ITERS ((ROWS * GG) / NTHREADS)   // 768 / 384 = 2
#define P2_ITERS (ROWS / TY)                // 6

__global__ __launch_bounds__(NTHREADS)
void bspline_flow_kernel(const float* __restrict__ in, float4* __restrict__ out)
{
    __shared__ float2 pys[ROWS * GG];   // 6 KB y-interpolated (pre-scaled) rows

    const int n       = blockIdx.x;           // image
    const int rowBase = blockIdx.y * ROWS;    // first row of this tile
    const int tid     = threadIdx.y * TX + threadIdx.x;
    const float coef  = (float)(GG - 1) / (float)GH;   // 31/192 (H==W)

    const float2* __restrict__ ctrl =
        reinterpret_cast<const float2*>(in) + (size_t)n * (GG * GG);

    // ---- Pass 1: y-axis blend (scaled by -192) into smem ----
    #pragma unroll
    for (int e = 0; e < P1_ITERS; e++) {
        const int idx = e * NTHREADS + tid;
        const int y = rowBase + (idx >> 5);   // global row
        const int j = idx & 31;               // ctrl column

        float qy = (float)y * coef;
        float fy = fminf(floorf(qy), (float)(GG - 2));
        int   iy = (int)fy;
        float ay = fminf(fmaxf(qy - fy, 0.0f), 1.0f);

        const float2* __restrict__ base = ctrl + iy * GG + j;
        float2 p0 = base[0];          // coalesced 256B row reads per warp (L2 hit)
        float2 p1 = base[GG];

        float2 r;
        r.x = fmaf(ay, p1.x - p0.x, p0.x) * -192.0f;   // -d * H folded in
        r.y = fmaf(ay, p1.y - p0.y, p0.y) * -192.0f;   // -d * W folded in
        pys[idx] = r;
    }
    __syncthreads();

    // ---- Pass 2: x-axis blend, write float4 (2 pixels) per iteration ----
    const int xb = threadIdx.x * 2;

    float qx0 = (float)(xb + 0) * coef;
    float fx0 = fminf(floorf(qx0), (float)(GG - 2));
    int   ix0 = (int)fx0;
    float ax0 = fminf(fmaxf(qx0 - fx0, 0.0f), 1.0f);

    float qx1 = (float)(xb + 1) * coef;
    float fx1 = fminf(floorf(qx1), (float)(GG - 2));
    int   ix1 = (int)fx1;
    float ax1 = fminf(fmaxf(qx1 - fx1, 0.0f), 1.0f);

    const float2* __restrict__ row = pys + threadIdx.y * GG;
    float4* __restrict__ dst = out + (size_t)n * (GH * (GW / 2))
                                   + (size_t)rowBase * (GW / 2)
                                   + threadIdx.y * TX + threadIdx.x;

    #pragma unroll
    for (int e = 0; e < P2_ITERS; e++) {
        float2 c0 = row[ix0];
        float2 c1 = row[ix0 + 1];
        float2 c2 = row[ix1];
        float2 c3 = row[ix1 + 1];

        float4 res;
        res.x = fmaf(ax0, c1.x - c0.x, c0.x);   // pixel 0, ch 0
        res.y = fmaf(ax0, c1.y - c0.y, c0.y);   // pixel 0, ch 1
        res.z = fmaf(ax1, c3.x - c2.x, c2.x);   // pixel 1, ch 0
        res.w = fmaf(ax1, c3.y - c2.y, c2.y);   // pixel 1, ch 1

        // streaming store: write-once data, evict-first in L2
        __stcs(dst, res);

        row += TY * GG;          // next row handled by this thread
        dst += TY * TX;
    }
}

extern "C" void kernel_launch(void* const* d_in, const int* in_sizes, int n_in,
                              void* d_out, int out_size)
{
    const float* in = (const float*)d_in[0];
    const int n_images = in_sizes[0] / (2 * GG * GG);   // 400
    dim3 grid(n_images, TILES);
    dim3 block(TX, TY);
    bspline_flow_kernel<<<grid, block>>>(in, (float4*)d_out);
}

// round 10
// speedup vs baseline: 1.1878x; 1.0014x over previous
#include <cuda_runtime.h>

// Bspline control-grid -> dense flow field, separable two-pass, tiled.
// N = 400 images, each split across 16 CTAs of 12 rows (grid 400x16 = 6400 CTAs).
//
// Steady-state model: harness graph-replay drains 118 MB of dirty output lines
// to DRAM per iteration -> sustained ~5.2 TB/s write BW at 22.5us; we are near
// the write-only HBM ceiling. Remaining slack = wave-tail quantization + pass-1
// serial head, both shrunk here by halving the CTA work quantum (TILES 8 -> 16).
//
// Pass 1: pys[y][j] = -192 * lerp_y(ctrl) for this CTA's 12 rows -> 3 KB smem,
//         exactly one element per thread (no loop).
// Pass 2: out[y][x] = lerp_x(pys[y]) -> 4 LDS.64 + 4 FFMA + 1 STG.128.CS per 2 px,
//         3 fully-unrolled iterations.

#define GH 192
#define GW 192
#define GG 32
#define TILES 16
#define ROWS (GH / TILES)     // 12 rows per CTA
#define TX 96                 // column pairs per row (192/2)
#define TY 4                  // row stride
#define NTHREADS (TX * TY)    // 384 == ROWS*GG (one pass-1 element per thread)
#define P2_ITERS (ROWS / TY)  // 3

__global__ __launch_bounds__(NTHREADS)
void bspline_flow_kernel(const float* __restrict__ in, float4* __restrict__ out)
{
    __shared__ float2 pys[ROWS * GG];   // 3 KB y-interpolated (pre-scaled) rows

    const int n       = blockIdx.x;           // image
    const int rowBase = blockIdx.y * ROWS;    // first row of this tile
    const int tid     = threadIdx.y * TX + threadIdx.x;
    const float coef  = (float)(GG - 1) / (float)GH;   // 31/192 (H==W)

    const float2* __restrict__ ctrl =
        reinterpret_cast<const float2*>(in) + (size_t)n * (GG * GG);

    // ---- Pass 1: y-axis blend (scaled by -192) into smem, 1 elem/thread ----
    {
        const int y = rowBase + (tid >> 5);   // global row
        const int j = tid & 31;               // ctrl column

        float qy = (float)y * coef;
        float fy = fminf(floorf(qy), (float)(GG - 2));
        int   iy = (int)fy;
        float ay = fminf(fmaxf(qy - fy, 0.0f), 1.0f);

        const float2* __restrict__ base = ctrl + iy * GG + j;
        float2 p0 = base[0];          // coalesced 256B row reads per warp (L2 hit)
        float2 p1 = base[GG];

        float2 r;
        r.x = fmaf(ay, p1.x - p0.x, p0.x) * -192.0f;   // -d * H folded in
        r.y = fmaf(ay, p1.y - p0.y, p0.y) * -192.0f;   // -d * W folded in
        pys[tid] = r;
    }
    __syncthreads();

    // ---- Pass 2: x-axis blend, write float4 (2 pixels) per iteration ----
    const int xb = threadIdx.x * 2;

    float qx0 = (float)(xb + 0) * coef;
    float fx0 = fminf(floorf(qx0), (float)(GG - 2));
    int   ix0 = (int)fx0;
    float ax0 = fminf(fmaxf(qx0 - fx0, 0.0f), 1.0f);

    float qx1 = (float)(xb + 1) * coef;
    float fx1 = fminf(floorf(qx1), (float)(GG - 2));
    int   ix1 = (int)fx1;
    float ax1 = fminf(fmaxf(qx1 - fx1, 0.0f), 1.0f);

    const float2* __restrict__ row = pys + threadIdx.y * GG;
    float4* __restrict__ dst = out + (size_t)n * (GH * (GW / 2))
                                   + (size_t)rowBase * (GW / 2)
                                   + threadIdx.y * TX + threadIdx.x;

    #pragma unroll
    for (int e = 0; e < P2_ITERS; e++) {
        float2 c0 = row[ix0];
        float2 c1 = row[ix0 + 1];
        float2 c2 = row[ix1];
        float2 c3 = row[ix1 + 1];

        float4 res;
        res.x = fmaf(ax0, c1.x - c0.x, c0.x);   // pixel 0, ch 0
        res.y = fmaf(ax0, c1.y - c0.y, c0.y);   // pixel 0, ch 1
        res.z = fmaf(ax1, c3.x - c2.x, c2.x);   // pixel 1, ch 0
        res.w = fmaf(ax1, c3.y - c2.y, c2.y);   // pixel 1, ch 1

        // streaming store: write-once data, evict-first in L2
        __stcs(dst, res);

        row += TY * GG;          // next row handled by this thread
        dst += TY * TX;
    }
}

extern "C" void kernel_launch(void* const* d_in, const int* in_sizes, int n_in,
                              void* d_out, int out_size)
{
    const float* in = (const float*)d_in[0];
    const int n_images = in_sizes[0] / (2 * GG * GG);   // 400
    dim3 grid(n_images, TILES);
    dim3 block(TX, TY);
    bspline_flow_kernel<<<grid, block>>>(in, (float4*)d_out);
}